// round 6
// baseline (speedup 1.0000x reference)
#include <cuda_runtime.h>
#include <math.h>

#define Bc   4
#define Sc   2048
#define HIDc 1024
#define Hc   16
#define Dc   64
#define MROWS (Bc*Sc)        // 8192
#define BHc  (Bc*Hc)         // 64
#define LOG2E 1.4426950408889634f

// Scratch (allocation-free __device__ globals)
__device__ float g_Q[(size_t)BHc * Sc * Dc];
__device__ float g_K[(size_t)BHc * Sc * Dc];
__device__ float g_V[(size_t)BHc * Sc * Dc];
__device__ float g_pm[(size_t)BHc * Sc * 16];
__device__ float g_pl[(size_t)BHc * Sc * 16];
__device__ float g_M [(size_t)BHc * Sc];
__device__ float g_Li[(size_t)BHc * Sc];

// ---------------------------------------------------------------------------
// tf32 helpers
// ---------------------------------------------------------------------------
__device__ __forceinline__ unsigned f2tf32(float x) {
    unsigned r;
    asm("cvt.rna.tf32.f32 %0, %1;" : "=r"(r) : "f"(x));
    return r;
}
__device__ __forceinline__ void split_tf32(float x, unsigned& hi, unsigned& lo) {
    hi = f2tf32(x);
    lo = f2tf32(x - __uint_as_float(hi));
}
__device__ __forceinline__ void mma_tf32(float c[4], const unsigned a[4], const unsigned b[2]) {
    asm("mma.sync.aligned.m16n8k8.row.col.f32.tf32.tf32.f32 "
        "{%0,%1,%2,%3},{%4,%5,%6,%7},{%8,%9},{%0,%1,%2,%3};"
        : "+f"(c[0]), "+f"(c[1]), "+f"(c[2]), "+f"(c[3])
        : "r"(a[0]), "r"(a[1]), "r"(a[2]), "r"(a[3]), "r"(b[0]), "r"(b[1]));
}

// Pair index: element with local k (0..31) lives at pair row (k>>3)*4 + (k&3),
// .x if ((k>>2)&1)==0 else .y — i.e. the (k, k+4) fragment pair in one uint2.

// ---------------------------------------------------------------------------
// Projection GEMM: C = X*W^T + bias, split-tf32 (3 mma).
// CTA 64x128, BK=32, 4 warps (2m x 2n). W pre-split+paired; X paired float2.
// ---------------------------------------------------------------------------
__global__ __launch_bounds__(128) void proj_kernel(
    const float* __restrict__ X, const float* __restrict__ W,
    const float* __restrict__ bias, float* __restrict__ out)
{
    __shared__ float2 XsP[16][76];
    __shared__ uint2  WhP[16][132];
    __shared__ uint2  WlP[16][132];

    const int tid  = threadIdx.x;
    const int lane = tid & 31;
    const int warp = tid >> 5;
    const int g    = lane >> 2;
    const int t4   = lane & 3;
    const int wm   = (warp >> 1) * 32;
    const int wn   = (warp & 1) * 64;
    const int m0   = blockIdx.y * 64;
    const int n0   = blockIdx.x * 128;

    float acc[2][8][4] = {};

    for (int k0 = 0; k0 < 1024; k0 += 32) {
        // X tile 64x32 -> paired float2
        #pragma unroll
        for (int it = 0; it < 4; it++) {
            const int idx = tid + it * 128;      // 0..511
            const int row = idx >> 3;            // 0..63
            const int c4  = (idx & 7) * 4;       // 0..28
            float4 a = *(const float4*)&X[(size_t)(m0 + row) * 1024 + k0 + c4];
            const int pr = (c4 >> 3) * 4;
            float v[4] = {a.x, a.y, a.z, a.w};
            if ((c4 & 4) == 0) {
                #pragma unroll
                for (int i = 0; i < 4; i++) XsP[pr + i][row].x = v[i];
            } else {
                #pragma unroll
                for (int i = 0; i < 4; i++) XsP[pr + i][row].y = v[i];
            }
        }
        // W tile 128x32 -> split hi/lo, paired
        #pragma unroll
        for (int it = 0; it < 8; it++) {
            const int idx = tid + it * 128;      // 0..1023
            const int row = idx >> 3;            // 0..127
            const int c4  = (idx & 7) * 4;
            float4 b = *(const float4*)&W[(size_t)(n0 + row) * 1024 + k0 + c4];
            const int pr = (c4 >> 3) * 4;
            float v[4] = {b.x, b.y, b.z, b.w};
            if ((c4 & 4) == 0) {
                #pragma unroll
                for (int i = 0; i < 4; i++) {
                    unsigned h, l; split_tf32(v[i], h, l);
                    WhP[pr + i][row].x = h; WlP[pr + i][row].x = l;
                }
            } else {
                #pragma unroll
                for (int i = 0; i < 4; i++) {
                    unsigned h, l; split_tf32(v[i], h, l);
                    WhP[pr + i][row].y = h; WlP[pr + i][row].y = l;
                }
            }
        }
        __syncthreads();

        #pragma unroll
        for (int ks = 0; ks < 4; ks++) {
            const int p = ks * 4 + t4;
            unsigned ah[2][4], al[2][4];
            #pragma unroll
            for (int i = 0; i < 2; i++) {
                const int r = wm + i * 16 + g;
                float2 q0 = XsP[p][r];
                float2 q1 = XsP[p][r + 8];
                split_tf32(q0.x, ah[i][0], al[i][0]);
                split_tf32(q1.x, ah[i][1], al[i][1]);
                split_tf32(q0.y, ah[i][2], al[i][2]);
                split_tf32(q1.y, ah[i][3], al[i][3]);
            }
            #pragma unroll
            for (int j = 0; j < 8; j++) {
                const int c = wn + j * 8 + g;
                uint2 wh = WhP[p][c];
                uint2 wl = WlP[p][c];
                unsigned bh_[2] = {wh.x, wh.y};
                unsigned bl_[2] = {wl.x, wl.y};
                #pragma unroll
                for (int i = 0; i < 2; i++) {
                    mma_tf32(acc[i][j], al[i], bh_);
                    mma_tf32(acc[i][j], ah[i], bl_);
                    mma_tf32(acc[i][j], ah[i], bh_);
                }
            }
        }
        __syncthreads();
    }

    #pragma unroll
    for (int i = 0; i < 2; i++) {
        #pragma unroll
        for (int j = 0; j < 8; j++) {
            const int n = n0 + wn + j * 8 + t4 * 2;
            const int h = n >> 6;
            const int d = n & 63;
            const float bv0 = bias[n];
            const float bv1 = bias[n + 1];
            const int m1 = m0 + wm + i * 16 + g;
            {
                const int b_ = m1 >> 11, s = m1 & 2047;
                *(float2*)&out[(((size_t)b_ * 16 + h) * 2048 + s) * 64 + d] =
                    make_float2(acc[i][j][0] + bv0, acc[i][j][1] + bv1);
            }
            {
                const int m2 = m1 + 8;
                const int b_ = m2 >> 11, s = m2 & 2047;
                *(float2*)&out[(((size_t)b_ * 16 + h) * 2048 + s) * 64 + d] =
                    make_float2(acc[i][j][2] + bv0, acc[i][j][3] + bv1);
            }
        }
    }
}

// ---------------------------------------------------------------------------
// Scores: s = scale*Q.K^T (split-tf32), mask, store raw s, emit partials.
// CTA 64x128, 4 warps each 16 rows. K pre-split+paired, Q paired float2.
// ---------------------------------------------------------------------------
__global__ __launch_bounds__(128) void scores_kernel(
    const float* __restrict__ Q, const float* __restrict__ K,
    const int* __restrict__ mask, float* __restrict__ attn)
{
    const int bh = blockIdx.x;
    const int n0 = blockIdx.y * 128;
    const int m0 = blockIdx.z * 64;
    const float* Qh = Q + (size_t)bh * Sc * Dc;
    const float* Kh_g = K + (size_t)bh * Sc * Dc;
    float* Ph = attn + (size_t)bh * Sc * Sc;

    __shared__ float2 QsP[16][76];
    __shared__ uint2  KhP[16][132];
    __shared__ uint2  KlP[16][132];

    const int tid  = threadIdx.x;
    const int lane = tid & 31;
    const int warp = tid >> 5;
    const int g    = lane >> 2;
    const int t4   = lane & 3;
    const int mw   = warp * 16;

    float acc[16][4] = {};

    #pragma unroll
    for (int k0 = 0; k0 < 64; k0 += 32) {
        #pragma unroll
        for (int it = 0; it < 4; it++) {
            const int idx = tid + it * 128;      // 0..511
            const int row = idx >> 3;            // 0..63
            const int c4  = (idx & 7) * 4;
            float4 a = *(const float4*)&Qh[(size_t)(m0 + row) * 64 + k0 + c4];
            const int pr = (c4 >> 3) * 4;
            float v[4] = {a.x, a.y, a.z, a.w};
            if ((c4 & 4) == 0) {
                #pragma unroll
                for (int i = 0; i < 4; i++) QsP[pr + i][row].x = v[i];
            } else {
                #pragma unroll
                for (int i = 0; i < 4; i++) QsP[pr + i][row].y = v[i];
            }
        }
        #pragma unroll
        for (int it = 0; it < 8; it++) {
            const int idx = tid + it * 128;      // 0..1023
            const int row = idx >> 3;            // 0..127
            const int c4  = (idx & 7) * 4;
            float4 b = *(const float4*)&Kh_g[(size_t)(n0 + row) * 64 + k0 + c4];
            const int pr = (c4 >> 3) * 4;
            float v[4] = {b.x, b.y, b.z, b.w};
            if ((c4 & 4) == 0) {
                #pragma unroll
                for (int i = 0; i < 4; i++) {
                    unsigned h, l; split_tf32(v[i], h, l);
                    KhP[pr + i][row].x = h; KlP[pr + i][row].x = l;
                }
            } else {
                #pragma unroll
                for (int i = 0; i < 4; i++) {
                    unsigned h, l; split_tf32(v[i], h, l);
                    KhP[pr + i][row].y = h; KlP[pr + i][row].y = l;
                }
            }
        }
        __syncthreads();

        #pragma unroll
        for (int ks = 0; ks < 4; ks++) {
            const int p = ks * 4 + t4;
            unsigned ah[4], al[4];
            const int r = mw + g;
            float2 q0 = QsP[p][r];
            float2 q1 = QsP[p][r + 8];
            split_tf32(q0.x, ah[0], al[0]);
            split_tf32(q1.x, ah[1], al[1]);
            split_tf32(q0.y, ah[2], al[2]);
            split_tf32(q1.y, ah[3], al[3]);
            #pragma unroll
            for (int j = 0; j < 16; j++) {
                const int c = j * 8 + g;
                uint2 kh = KhP[p][c];
                uint2 kl = KlP[p][c];
                unsigned bh_[2] = {kh.x, kh.y};
                unsigned bl_[2] = {kl.x, kl.y};
                mma_tf32(acc[j], al, bh_);
                mma_tf32(acc[j], ah, bl_);
                mma_tf32(acc[j], ah, bh_);
            }
        }
        __syncthreads();
    }

    const int b_ = bh >> 4;
    const int* mb = mask + (size_t)b_ * Sc * Sc;
    const float scale = 0.125f;
    const int r0 = m0 + mw + g;
    const int r1 = r0 + 8;

    float mx0 = -3.4e38f, mx1 = -3.4e38f;
    #pragma unroll
    for (int j = 0; j < 16; j++) {
        const int col = n0 + j * 8 + t4 * 2;
        const int2 mm0 = *(const int2*)&mb[(size_t)r0 * Sc + col];
        const int2 mm1 = *(const int2*)&mb[(size_t)r1 * Sc + col];
        acc[j][0] = mm0.x ? acc[j][0] * scale : -1e9f;
        acc[j][1] = mm0.y ? acc[j][1] * scale : -1e9f;
        acc[j][2] = mm1.x ? acc[j][2] * scale : -1e9f;
        acc[j][3] = mm1.y ? acc[j][3] * scale : -1e9f;
        *(float2*)&Ph[(size_t)r0 * Sc + col] = make_float2(acc[j][0], acc[j][1]);
        *(float2*)&Ph[(size_t)r1 * Sc + col] = make_float2(acc[j][2], acc[j][3]);
        mx0 = fmaxf(mx0, fmaxf(acc[j][0], acc[j][1]));
        mx1 = fmaxf(mx1, fmaxf(acc[j][2], acc[j][3]));
    }
    mx0 = fmaxf(mx0, __shfl_xor_sync(0xFFFFFFFFu, mx0, 1));
    mx0 = fmaxf(mx0, __shfl_xor_sync(0xFFFFFFFFu, mx0, 2));
    mx1 = fmaxf(mx1, __shfl_xor_sync(0xFFFFFFFFu, mx1, 1));
    mx1 = fmaxf(mx1, __shfl_xor_sync(0xFFFFFFFFu, mx1, 2));

    float s0 = 0.0f, s1 = 0.0f;
    #pragma unroll
    for (int j = 0; j < 16; j++) {
        s0 += exp2f((acc[j][0] - mx0) * LOG2E) + exp2f((acc[j][1] - mx0) * LOG2E);
        s1 += exp2f((acc[j][2] - mx1) * LOG2E) + exp2f((acc[j][3] - mx1) * LOG2E);
    }
    s0 += __shfl_xor_sync(0xFFFFFFFFu, s0, 1);
    s0 += __shfl_xor_sync(0xFFFFFFFFu, s0, 2);
    s1 += __shfl_xor_sync(0xFFFFFFFFu, s1, 1);
    s1 += __shfl_xor_sync(0xFFFFFFFFu, s1, 2);

    if (t4 == 0) {
        g_pm[((size_t)bh * Sc + r0) * 16 + blockIdx.y] = mx0;
        g_pl[((size_t)bh * Sc + r0) * 16 + blockIdx.y] = s0;
        g_pm[((size_t)bh * Sc + r1) * 16 + blockIdx.y] = mx1;
        g_pl[((size_t)bh * Sc + r1) * 16 + blockIdx.y] = s1;
    }
}

// ---------------------------------------------------------------------------
__global__ __launch_bounds__(256) void reduce_ml_kernel()
{
    const size_t r = (size_t)blockIdx.x * 256 + threadIdx.x;
    float m = -3.4e38f;
    float pm[16];
    #pragma unroll
    for (int t = 0; t < 16; t++) {
        pm[t] = g_pm[r * 16 + t];
        m = fmaxf(m, pm[t]);
    }
    float l = 0.0f;
    #pragma unroll
    for (int t = 0; t < 16; t++)
        l += g_pl[r * 16 + t] * exp2f((pm[t] - m) * LOG2E);
    g_M[r]  = m;
    g_Li[r] = 1.0f / l;
}

// ---------------------------------------------------------------------------
// PV: p = exp(s-m)*invl (attn in place), ctx = p @ V. Single tf32 mma.
// P and V pre-converted to tf32, pair-packed. CTA 128 rows, 8 warps.
// ---------------------------------------------------------------------------
__global__ __launch_bounds__(256) void pv_kernel(
    float* __restrict__ attn, const float* __restrict__ V,
    float* __restrict__ ctx)
{
    const int bh = blockIdx.x;
    const int m0 = blockIdx.y * 128;
    float* Ph = attn + (size_t)bh * Sc * Sc;
    const float* Vh = V + (size_t)bh * Sc * Dc;

    __shared__ uint2 PsP[16][132];
    __shared__ uint2 VsP[16][68];
    __shared__ float smx[128], sli[128];

    const int tid  = threadIdx.x;
    const int lane = tid & 31;
    const int warp = tid >> 5;
    const int g    = lane >> 2;
    const int t4   = lane & 3;
    const int mw   = warp * 16;

    if (tid < 128) {
        const size_t r = (size_t)bh * Sc + m0 + tid;
        smx[tid] = g_M[r];
        sli[tid] = g_Li[r];
    }
    __syncthreads();

    float acc[8][4] = {};

    for (int k0 = 0; k0 < 2048; k0 += 32) {
        #pragma unroll
        for (int it = 0; it < 4; it++) {
            const int idx = tid + it * 256;      // 0..1023
            const int row = idx >> 3;            // 0..127
            const int c4  = (idx & 7) * 4;
            float* gp = &Ph[(size_t)(m0 + row) * Sc + k0 + c4];
            float4 s = *(const float4*)gp;
            const float mr = smx[row];
            const float il = sli[row];
            float4 pv;
            pv.x = exp2f((s.x - mr) * LOG2E) * il;
            pv.y = exp2f((s.y - mr) * LOG2E) * il;
            pv.z = exp2f((s.z - mr) * LOG2E) * il;
            pv.w = exp2f((s.w - mr) * LOG2E) * il;
            *(float4*)gp = pv;
            const int pr = (c4 >> 3) * 4;
            float v[4] = {pv.x, pv.y, pv.z, pv.w};
            if ((c4 & 4) == 0) {
                #pragma unroll
                for (int i = 0; i < 4; i++) PsP[pr + i][row].x = f2tf32(v[i]);
            } else {
                #pragma unroll
                for (int i = 0; i < 4; i++) PsP[pr + i][row].y = f2tf32(v[i]);
            }
        }
        #pragma unroll
        for (int it = 0; it < 2; it++) {
            const int idx = tid + it * 256;      // 0..511
            const int vr  = idx >> 4;            // 0..31 (k)
            const int vc  = (idx & 15) * 4;      // 0..60 (col)
            float4 v = *(const float4*)&Vh[(size_t)(k0 + vr) * 64 + vc];
            const int pr = (vr >> 3) * 4 + (vr & 3);
            float w[4] = {v.x, v.y, v.z, v.w};
            if (((vr >> 2) & 1) == 0) {
                #pragma unroll
                for (int i = 0; i < 4; i++) VsP[pr][vc + i].x = f2tf32(w[i]);
            } else {
                #pragma unroll
                for (int i = 0; i < 4; i++) VsP[pr][vc + i].y = f2tf32(w[i]);
            }
        }
        __syncthreads();

        #pragma unroll
        for (int ks = 0; ks < 4; ks++) {
            const int p = ks * 4 + t4;
            const int r = mw + g;
            uint2 pa0 = PsP[p][r];
            uint2 pa1 = PsP[p][r + 8];
            unsigned a[4] = {pa0.x, pa1.x, pa0.y, pa1.y};
            #pragma unroll
            for (int j = 0; j < 8; j++) {
                uint2 vb = VsP[p][j * 8 + g];
                unsigned b[2] = {vb.x, vb.y};
                mma_tf32(acc[j], a, b);
            }
        }
        __syncthreads();
    }

    const int b_ = bh >> 4;
    const int h  = bh & 15;
    const int r0 = m0 + mw + g;
    const int r1 = r0 + 8;
    #pragma unroll
    for (int j = 0; j < 8; j++) {
        const int d = j * 8 + t4 * 2;
        *(float2*)&ctx[((size_t)b_ * 2048 + r0) * 1024 + h * 64 + d] =
            make_float2(acc[j][0], acc[j][1]);
        *(float2*)&ctx[((size_t)b_ * 2048 + r1) * 1024 + h * 64 + d] =
            make_float2(acc[j][2], acc[j][3]);
    }
}

// ---------------------------------------------------------------------------
extern "C" void kernel_launch(void* const* d_in, const int* in_sizes, int n_in,
                              void* d_out, int out_size)
{
    (void)in_sizes; (void)n_in; (void)out_size;

    const float* query  = (const float*)d_in[0];
    const float* key_in = (const float*)d_in[1];
    const float* value  = (const float*)d_in[2];
    const int*   mask   = (const int*)  d_in[3];
    const float* w_q    = (const float*)d_in[4];
    const float* b_q    = (const float*)d_in[5];
    const float* w_k    = (const float*)d_in[6];
    const float* b_k    = (const float*)d_in[7];
    const float* w_v    = (const float*)d_in[8];
    const float* b_v    = (const float*)d_in[9];

    float* ctx  = (float*)d_out;
    float* attn = (float*)d_out + (size_t)Bc * Sc * HIDc;

    float *Q, *K, *V;
    cudaGetSymbolAddress((void**)&Q, g_Q);
    cudaGetSymbolAddress((void**)&K, g_K);
    cudaGetSymbolAddress((void**)&V, g_V);

    dim3 gp(HIDc / 128, MROWS / 64);             // (8, 128)
    proj_kernel<<<gp, 128>>>(query,  w_q, b_q, Q);
    proj_kernel<<<gp, 128>>>(key_in, w_k, b_k, K);
    proj_kernel<<<gp, 128>>>(value,  w_v, b_v, V);

    dim3 gs(BHc, Sc / 128, Sc / 64);             // (64, 16, 32)
    scores_kernel<<<gs, 128>>>(Q, K, mask, attn);

    reduce_ml_kernel<<<(BHc * Sc) / 256, 256>>>();

    dim3 gv(BHc, Sc / 128);                      // (64, 16)
    pv_kernel<<<gv, 256>>>(attn, V, ctx);
}

// round 7
// speedup vs baseline: 1.7338x; 1.7338x over previous
#include <cuda_runtime.h>
#include <cuda_bf16.h>
#include <math.h>

#define Bc   4
#define Sc   2048
#define HIDc 1024
#define Hc   16
#define Dc   64
#define MROWS (Bc*Sc)        // 8192
#define BHc  (Bc*Hc)         // 64
#define LOG2E 1.4426950408889634f

// ---------------------------------------------------------------------------
// Scratch (allocation-free __device__ globals)
// ---------------------------------------------------------------------------
__device__ unsigned g_xh[(size_t)MROWS * 512];       // input  split hi (pairs)
__device__ unsigned g_xl[(size_t)MROWS * 512];       // input  split lo
__device__ unsigned g_wh[(size_t)HIDc * 512];        // weight split hi
__device__ unsigned g_wl[(size_t)HIDc * 512];        // weight split lo
__device__ unsigned g_Qh[(size_t)BHc * Sc * 32];     // Q packed bf16 hi pairs
__device__ unsigned g_Ql[(size_t)BHc * Sc * 32];
__device__ unsigned g_Kh[(size_t)BHc * Sc * 32];
__device__ unsigned g_Kl[(size_t)BHc * Sc * 32];
__device__ float    g_V [(size_t)BHc * Sc * Dc];
__device__ float    g_pm[(size_t)BHc * Sc * 32];     // partial max per 64-col block
__device__ float    g_pl[(size_t)BHc * Sc * 32];     // partial sumexp
__device__ float    g_M [(size_t)BHc * Sc];
__device__ float    g_Li[(size_t)BHc * Sc];

// ---------------------------------------------------------------------------
// helpers
// ---------------------------------------------------------------------------
__device__ __forceinline__ unsigned f2tf32(float x) {
    unsigned r;
    asm("cvt.rna.tf32.f32 %0, %1;" : "=r"(r) : "f"(x));
    return r;
}
__device__ __forceinline__ void mma_tf32(float c[4], const unsigned a[4], const unsigned b[2]) {
    asm("mma.sync.aligned.m16n8k8.row.col.f32.tf32.tf32.f32 "
        "{%0,%1,%2,%3},{%4,%5,%6,%7},{%8,%9},{%0,%1,%2,%3};"
        : "+f"(c[0]), "+f"(c[1]), "+f"(c[2]), "+f"(c[3])
        : "r"(a[0]), "r"(a[1]), "r"(a[2]), "r"(a[3]), "r"(b[0]), "r"(b[1]));
}
__device__ __forceinline__ void mma_bf16(float c[4], const unsigned a[4], const unsigned b[2]) {
    asm("mma.sync.aligned.m16n8k16.row.col.f32.bf16.bf16.f32 "
        "{%0,%1,%2,%3},{%4,%5,%6,%7},{%8,%9},{%0,%1,%2,%3};"
        : "+f"(c[0]), "+f"(c[1]), "+f"(c[2]), "+f"(c[3])
        : "r"(a[0]), "r"(a[1]), "r"(a[2]), "r"(a[3]), "r"(b[0]), "r"(b[1]));
}
// split (x,y) into packed bf16 hi pair and lo pair (lo = residual)
__device__ __forceinline__ void split_pack_bf16(float x, float y, unsigned& h, unsigned& l) {
    __nv_bfloat16 hx = __float2bfloat16(x);
    __nv_bfloat16 hy = __float2bfloat16(y);
    __nv_bfloat162 hp; hp.x = hx; hp.y = hy;
    h = *reinterpret_cast<unsigned*>(&hp);
    __nv_bfloat162 lp = __floats2bfloat162_rn(x - __bfloat162float(hx),
                                              y - __bfloat162float(hy));
    l = *reinterpret_cast<unsigned*>(&lp);
}

// ---------------------------------------------------------------------------
// Pre-split: float array -> packed bf16 hi/lo pair arrays
// ---------------------------------------------------------------------------
__global__ __launch_bounds__(256) void presplit_kernel(
    const float* __restrict__ src, unsigned* __restrict__ hi,
    unsigned* __restrict__ lo, int n2)
{
    const int i = blockIdx.x * 256 + threadIdx.x;
    if (i < n2) {
        float2 v = ((const float2*)src)[i];
        unsigned h, l;
        split_pack_bf16(v.x, v.y, h, l);
        hi[i] = h; lo[i] = l;
    }
}

// ---------------------------------------------------------------------------
// Projection: C = X*W^T + bias via bf16x3 mma (m16n8k16).
// CTA 64x128, 4 warps (2m x 2n), warp tile 32x64. BK=32 floats (16 pairs).
// mode 1: write packed bf16 hi/lo into (outh,outl) [bh][s][d2]
// mode 0: write float into outf [bh][s][64]
// ---------------------------------------------------------------------------
__global__ __launch_bounds__(128) void proj_kernel(
    const unsigned* __restrict__ Xh, const unsigned* __restrict__ Xl,
    const unsigned* __restrict__ Wh, const unsigned* __restrict__ Wl,
    const float* __restrict__ bias,
    float* __restrict__ outf, unsigned* __restrict__ outh,
    unsigned* __restrict__ outl, int mode)
{
    __shared__ unsigned Ah[16][72], Al[16][72];
    __shared__ unsigned Bh[16][136], Bl[16][136];

    const int tid  = threadIdx.x;
    const int lane = tid & 31;
    const int warp = tid >> 5;
    const int g    = lane >> 2;
    const int t4   = lane & 3;
    const int wm   = (warp >> 1) * 32;
    const int wn   = (warp & 1) * 64;
    const int m0   = blockIdx.y * 64;
    const int n0   = blockIdx.x * 128;

    float acc[2][8][4] = {};

    for (int it0 = 0; it0 < 32; it0++) {
        const int k0p = it0 * 16;                 // pair offset
        // X tile 64 rows x 16 pairs
        #pragma unroll
        for (int it = 0; it < 2; it++) {
            const int idx = tid + it * 128;       // 0..255
            const int row = idx >> 2;             // 0..63
            const int q4  = (idx & 3) * 4;
            uint4 h = *(const uint4*)&Xh[(size_t)(m0 + row) * 512 + k0p + q4];
            uint4 l = *(const uint4*)&Xl[(size_t)(m0 + row) * 512 + k0p + q4];
            Ah[q4+0][row] = h.x; Ah[q4+1][row] = h.y; Ah[q4+2][row] = h.z; Ah[q4+3][row] = h.w;
            Al[q4+0][row] = l.x; Al[q4+1][row] = l.y; Al[q4+2][row] = l.z; Al[q4+3][row] = l.w;
        }
        // W tile 128 rows x 16 pairs
        #pragma unroll
        for (int it = 0; it < 4; it++) {
            const int idx = tid + it * 128;       // 0..511
            const int row = idx >> 2;             // 0..127
            const int q4  = (idx & 3) * 4;
            uint4 h = *(const uint4*)&Wh[(size_t)(n0 + row) * 512 + k0p + q4];
            uint4 l = *(const uint4*)&Wl[(size_t)(n0 + row) * 512 + k0p + q4];
            Bh[q4+0][row] = h.x; Bh[q4+1][row] = h.y; Bh[q4+2][row] = h.z; Bh[q4+3][row] = h.w;
            Bl[q4+0][row] = l.x; Bl[q4+1][row] = l.y; Bl[q4+2][row] = l.z; Bl[q4+3][row] = l.w;
        }
        __syncthreads();

        #pragma unroll
        for (int st = 0; st < 2; st++) {
            const int kb = st * 8;
            unsigned ah[2][4], al[2][4];
            #pragma unroll
            for (int i = 0; i < 2; i++) {
                const int r = wm + i * 16 + g;
                ah[i][0] = Ah[kb + t4    ][r]; ah[i][1] = Ah[kb + t4    ][r + 8];
                ah[i][2] = Ah[kb + t4 + 4][r]; ah[i][3] = Ah[kb + t4 + 4][r + 8];
                al[i][0] = Al[kb + t4    ][r]; al[i][1] = Al[kb + t4    ][r + 8];
                al[i][2] = Al[kb + t4 + 4][r]; al[i][3] = Al[kb + t4 + 4][r + 8];
            }
            #pragma unroll
            for (int j = 0; j < 8; j++) {
                const int c = wn + j * 8 + g;
                unsigned bh_[2] = {Bh[kb + t4][c], Bh[kb + t4 + 4][c]};
                unsigned bl_[2] = {Bl[kb + t4][c], Bl[kb + t4 + 4][c]};
                #pragma unroll
                for (int i = 0; i < 2; i++) {
                    mma_bf16(acc[i][j], al[i], bh_);
                    mma_bf16(acc[i][j], ah[i], bl_);
                    mma_bf16(acc[i][j], ah[i], bh_);
                }
            }
        }
        __syncthreads();
    }

    #pragma unroll
    for (int i = 0; i < 2; i++) {
        #pragma unroll
        for (int j = 0; j < 8; j++) {
            const int n = wn + j * 8 + t4 * 2;        // within 128-tile, even
            const int ng = n0 + n;
            const int h = ng >> 6;
            const int d = ng & 63;
            const float bv0 = bias[ng];
            const float bv1 = bias[ng + 1];
            const int m1 = m0 + wm + i * 16 + g;
            const int m2 = m1 + 8;
            float v0 = acc[i][j][0] + bv0, v1 = acc[i][j][1] + bv1;
            float v2 = acc[i][j][2] + bv0, v3 = acc[i][j][3] + bv1;
            if (mode) {
                const int d2 = d >> 1;
                unsigned hh, ll;
                {
                    const int b_ = m1 >> 11, s = m1 & 2047;
                    const size_t o = ((size_t)(b_ * 16 + h) * 2048 + s) * 32 + d2;
                    split_pack_bf16(v0, v1, hh, ll);
                    outh[o] = hh; outl[o] = ll;
                }
                {
                    const int b_ = m2 >> 11, s = m2 & 2047;
                    const size_t o = ((size_t)(b_ * 16 + h) * 2048 + s) * 32 + d2;
                    split_pack_bf16(v2, v3, hh, ll);
                    outh[o] = hh; outl[o] = ll;
                }
            } else {
                {
                    const int b_ = m1 >> 11, s = m1 & 2047;
                    *(float2*)&outf[(((size_t)b_ * 16 + h) * 2048 + s) * 64 + d] =
                        make_float2(v0, v1);
                }
                {
                    const int b_ = m2 >> 11, s = m2 & 2047;
                    *(float2*)&outf[(((size_t)b_ * 16 + h) * 2048 + s) * 64 + d] =
                        make_float2(v2, v3);
                }
            }
        }
    }
}

// ---------------------------------------------------------------------------
// Scores: s = scale*Q.K^T via bf16x3, mask fill, store raw s, emit per-row
// per-64-col (max, sumexp) partials. CTA 64x128, 4 warps (2m x 2n).
// Grid: (bh, ntile128=16, mtile64=32).
// ---------------------------------------------------------------------------
__global__ __launch_bounds__(128) void scores_kernel(
    const int* __restrict__ mask, float* __restrict__ attn)
{
    const int bh = blockIdx.x;
    const int n0 = blockIdx.y * 128;
    const int m0 = blockIdx.z * 64;
    const unsigned* Qh_g = g_Qh + (size_t)bh * Sc * 32;
    const unsigned* Ql_g = g_Ql + (size_t)bh * Sc * 32;
    const unsigned* Kh_g = g_Kh + (size_t)bh * Sc * 32;
    const unsigned* Kl_g = g_Kl + (size_t)bh * Sc * 32;
    float* Ph = attn + (size_t)bh * Sc * Sc;

    __shared__ unsigned Ah[16][72], Al[16][72];
    __shared__ unsigned Bh[16][136], Bl[16][136];

    const int tid  = threadIdx.x;
    const int lane = tid & 31;
    const int warp = tid >> 5;
    const int g    = lane >> 2;
    const int t4   = lane & 3;
    const int wm   = (warp >> 1) * 32;
    const int wn   = (warp & 1) * 64;

    float acc[2][8][4] = {};

    #pragma unroll
    for (int it0 = 0; it0 < 2; it0++) {
        const int k0p = it0 * 16;
        #pragma unroll
        for (int it = 0; it < 2; it++) {
            const int idx = tid + it * 128;
            const int row = idx >> 2;             // 0..63
            const int q4  = (idx & 3) * 4;
            uint4 h = *(const uint4*)&Qh_g[(size_t)(m0 + row) * 32 + k0p + q4];
            uint4 l = *(const uint4*)&Ql_g[(size_t)(m0 + row) * 32 + k0p + q4];
            Ah[q4+0][row] = h.x; Ah[q4+1][row] = h.y; Ah[q4+2][row] = h.z; Ah[q4+3][row] = h.w;
            Al[q4+0][row] = l.x; Al[q4+1][row] = l.y; Al[q4+2][row] = l.z; Al[q4+3][row] = l.w;
        }
        #pragma unroll
        for (int it = 0; it < 4; it++) {
            const int idx = tid + it * 128;
            const int row = idx >> 2;             // 0..127
            const int q4  = (idx & 3) * 4;
            uint4 h = *(const uint4*)&Kh_g[(size_t)(n0 + row) * 32 + k0p + q4];
            uint4 l = *(const uint4*)&Kl_g[(size_t)(n0 + row) * 32 + k0p + q4];
            Bh[q4+0][row] = h.x; Bh[q4+1][row] = h.y; Bh[q4+2][row] = h.z; Bh[q4+3][row] = h.w;
            Bl[q4+0][row] = l.x; Bl[q4+1][row] = l.y; Bl[q4+2][row] = l.z; Bl[q4+3][row] = l.w;
        }
        __syncthreads();

        #pragma unroll
        for (int st = 0; st < 2; st++) {
            const int kb = st * 8;
            unsigned ah[2][4], al[2][4];
            #pragma unroll
            for (int i = 0; i < 2; i++) {
                const int r = wm + i * 16 + g;
                ah[i][0] = Ah[kb + t4    ][r]; ah[i][1] = Ah[kb + t4    ][r + 8];
                ah[i][2] = Ah[kb + t4 + 4][r]; ah[i][3] = Ah[kb + t4 + 4][r + 8];
                al[i][0] = Al[kb + t4    ][r]; al[i][1] = Al[kb + t4    ][r + 8];
                al[i][2] = Al[kb + t4 + 4][r]; al[i][3] = Al[kb + t4 + 4][r + 8];
            }
            #pragma unroll
            for (int j = 0; j < 8; j++) {
                const int c = wn + j * 8 + g;
                unsigned bh_[2] = {Bh[kb + t4][c], Bh[kb + t4 + 4][c]};
                unsigned bl_[2] = {Bl[kb + t4][c], Bl[kb + t4 + 4][c]};
                #pragma unroll
                for (int i = 0; i < 2; i++) {
                    mma_bf16(acc[i][j], al[i], bh_);
                    mma_bf16(acc[i][j], ah[i], bl_);
                    mma_bf16(acc[i][j], ah[i], bh_);
                }
            }
        }
        __syncthreads();
    }

    // epilogue: scale + mask + store raw s; per-row (max,sumexp) over 64 cols
    const int b_ = bh >> 4;
    const int* mb = mask + (size_t)b_ * Sc * Sc;
    const float scale = 0.125f;
    const int nt = blockIdx.y * 2 + (wn >> 6);    // 64-col partial index

    #pragma unroll
    for (int i = 0; i < 2; i++) {
        const int r0 = m0 + wm + i * 16 + g;
        const int r1 = r0 + 8;
        float mx0 = -3.4e38f, mx1 = -3.4e38f;
        #pragma unroll
        for (int j = 0; j < 8; j++) {
            const int col = n0 + wn + j * 8 + t4 * 2;
            const int2 mm0 = *(const int2*)&mb[(size_t)r0 * Sc + col];
            const int2 mm1 = *(const int2*)&mb[(size_t)r1 * Sc + col];
            acc[i][j][0] = mm0.x ? acc[i][j][0] * scale : -1e9f;
            acc[i][j][1] = mm0.y ? acc[i][j][1] * scale : -1e9f;
            acc[i][j][2] = mm1.x ? acc[i][j][2] * scale : -1e9f;
            acc[i][j][3] = mm1.y ? acc[i][j][3] * scale : -1e9f;
            *(float2*)&Ph[(size_t)r0 * Sc + col] = make_float2(acc[i][j][0], acc[i][j][1]);
            *(float2*)&Ph[(size_t)r1 * Sc + col] = make_float2(acc[i][j][2], acc[i][j][3]);
            mx0 = fmaxf(mx0, fmaxf(acc[i][j][0], acc[i][j][1]));
            mx1 = fmaxf(mx1, fmaxf(acc[i][j][2], acc[i][j][3]));
        }
        mx0 = fmaxf(mx0, __shfl_xor_sync(0xFFFFFFFFu, mx0, 1));
        mx0 = fmaxf(mx0, __shfl_xor_sync(0xFFFFFFFFu, mx0, 2));
        mx1 = fmaxf(mx1, __shfl_xor_sync(0xFFFFFFFFu, mx1, 1));
        mx1 = fmaxf(mx1, __shfl_xor_sync(0xFFFFFFFFu, mx1, 2));

        float s0 = 0.0f, s1 = 0.0f;
        #pragma unroll
        for (int j = 0; j < 8; j++) {
            s0 += exp2f((acc[i][j][0] - mx0) * LOG2E) + exp2f((acc[i][j][1] - mx0) * LOG2E);
            s1 += exp2f((acc[i][j][2] - mx1) * LOG2E) + exp2f((acc[i][j][3] - mx1) * LOG2E);
        }
        s0 += __shfl_xor_sync(0xFFFFFFFFu, s0, 1);
        s0 += __shfl_xor_sync(0xFFFFFFFFu, s0, 2);
        s1 += __shfl_xor_sync(0xFFFFFFFFu, s1, 1);
        s1 += __shfl_xor_sync(0xFFFFFFFFu, s1, 2);

        if (t4 == 0) {
            g_pm[((size_t)bh * Sc + r0) * 32 + nt] = mx0;
            g_pl[((size_t)bh * Sc + r0) * 32 + nt] = s0;
            g_pm[((size_t)bh * Sc + r1) * 32 + nt] = mx1;
            g_pl[((size_t)bh * Sc + r1) * 32 + nt] = s1;
        }
    }
}

// ---------------------------------------------------------------------------
// Combine 32 (m,l) partials per row -> final m, 1/l
// ---------------------------------------------------------------------------
__global__ __launch_bounds__(256) void reduce_ml_kernel()
{
    const size_t r = (size_t)blockIdx.x * 256 + threadIdx.x;
    float m = -3.4e38f;
    float pm[32];
    #pragma unroll
    for (int t = 0; t < 32; t++) {
        pm[t] = g_pm[r * 32 + t];
        m = fmaxf(m, pm[t]);
    }
    float l = 0.0f;
    #pragma unroll
    for (int t = 0; t < 32; t++)
        l += g_pl[r * 32 + t] * exp2f((pm[t] - m) * LOG2E);
    g_M[r]  = m;
    g_Li[r] = 1.0f / l;
}

// ---------------------------------------------------------------------------
// PV: p = exp(s-m)*invl (attn in place), ctx = p @ V. Single tf32 mma.
// CTA 128 rows x 64 cols, 8 warps each 16 rows. Conflict-free strides.
// ---------------------------------------------------------------------------
__global__ __launch_bounds__(256) void pv_kernel(
    float* __restrict__ attn, const float* __restrict__ V,
    float* __restrict__ ctx)
{
    const int bh = blockIdx.x;
    const int m0 = blockIdx.y * 128;
    float* Ph = attn + (size_t)bh * Sc * Sc;
    const float* Vh = V + (size_t)bh * Sc * Dc;

    __shared__ unsigned Ps[32][136];
    __shared__ unsigned Vs[32][72];
    __shared__ float smx[128], sli[128];

    const int tid  = threadIdx.x;
    const int lane = tid & 31;
    const int warp = tid >> 5;
    const int g    = lane >> 2;
    const int t4   = lane & 3;
    const int mw   = warp * 16;

    if (tid < 128) {
        const size_t r = (size_t)bh * Sc + m0 + tid;
        smx[tid] = g_M[r];
        sli[tid] = g_Li[r];
    }
    __syncthreads();

    float acc[8][4] = {};

    for (int k0 = 0; k0 < 2048; k0 += 32) {
        #pragma unroll
        for (int it = 0; it < 4; it++) {
            const int idx = tid + it * 256;
            const int row = idx >> 3;
            const int c4  = (idx & 7) * 4;
            float* gp = &Ph[(size_t)(m0 + row) * Sc + k0 + c4];
            float4 s = *(const float4*)gp;
            const float mr = smx[row];
            const float il = sli[row];
            float4 p;
            p.x = exp2f((s.x - mr) * LOG2E) * il;
            p.y = exp2f((s.y - mr) * LOG2E) * il;
            p.z = exp2f((s.z - mr) * LOG2E) * il;
            p.w = exp2f((s.w - mr) * LOG2E) * il;
            *(float4*)gp = p;
            Ps[c4 + 0][row] = f2tf32(p.x);
            Ps[c4 + 1][row] = f2tf32(p.y);
            Ps[c4 + 2][row] = f2tf32(p.z);
            Ps[c4 + 3][row] = f2tf32(p.w);
        }
        #pragma unroll
        for (int it = 0; it < 2; it++) {
            const int idx = tid + it * 256;
            const int vr  = idx >> 4;
            const int vc  = (idx & 15) * 4;
            float4 v = *(const float4*)&Vh[(size_t)(k0 + vr) * 64 + vc];
            Vs[vr][vc + 0] = f2tf32(v.x);
            Vs[vr][vc + 1] = f2tf32(v.y);
            Vs[vr][vc + 2] = f2tf32(v.z);
            Vs[vr][vc + 3] = f2tf32(v.w);
        }
        __syncthreads();

        #pragma unroll
        for (int ks = 0; ks < 4; ks++) {
            const int kb = ks * 8;
            unsigned a[4];
            const int r = mw + g;
            a[0] = Ps[kb + t4    ][r];
            a[1] = Ps[kb + t4    ][r + 8];
            a[2] = Ps[kb + t4 + 4][r];
            a[3] = Ps[kb + t4 + 4][r + 8];
            #pragma unroll
            for (int j = 0; j < 8; j++) {
                unsigned b[2];
                b[0] = Vs[kb + t4    ][j * 8 + g];
                b[1] = Vs[kb + t4 + 4][j * 8 + g];
                mma_tf32(acc[j], a, b);
            }
        }
        __syncthreads();
    }

    const int b_ = bh >> 4;
    const int h  = bh & 15;
    const int r0 = m0 + mw + g;
    const int r1 = r0 + 8;
    #pragma unroll
    for (int j = 0; j < 8; j++) {
        const int d = j * 8 + t4 * 2;
        *(float2*)&ctx[((size_t)b_ * 2048 + r0) * 1024 + h * 64 + d] =
            make_float2(acc[j][0], acc[j][1]);
        *(float2*)&ctx[((size_t)b_ * 2048 + r1) * 1024 + h * 64 + d] =
            make_float2(acc[j][2], acc[j][3]);
    }
}

// ---------------------------------------------------------------------------
extern "C" void kernel_launch(void* const* d_in, const int* in_sizes, int n_in,
                              void* d_out, int out_size)
{
    (void)in_sizes; (void)n_in; (void)out_size;

    const float* query  = (const float*)d_in[0];
    const float* key_in = (const float*)d_in[1];
    const float* value  = (const float*)d_in[2];
    const int*   mask   = (const int*)  d_in[3];
    const float* w_q    = (const float*)d_in[4];
    const float* b_q    = (const float*)d_in[5];
    const float* w_k    = (const float*)d_in[6];
    const float* b_k    = (const float*)d_in[7];
    const float* w_v    = (const float*)d_in[8];
    const float* b_v    = (const float*)d_in[9];

    float* ctx  = (float*)d_out;
    float* attn = (float*)d_out + (size_t)Bc * Sc * HIDc;

    unsigned *xh, *xl, *wh, *wl, *Qh, *Ql, *Kh, *Kl;
    float *V;
    cudaGetSymbolAddress((void**)&xh, g_xh);
    cudaGetSymbolAddress((void**)&xl, g_xl);
    cudaGetSymbolAddress((void**)&wh, g_wh);
    cudaGetSymbolAddress((void**)&wl, g_wl);
    cudaGetSymbolAddress((void**)&Qh, g_Qh);
    cudaGetSymbolAddress((void**)&Ql, g_Ql);
    cudaGetSymbolAddress((void**)&Kh, g_Kh);
    cudaGetSymbolAddress((void**)&Kl, g_Kl);
    cudaGetSymbolAddress((void**)&V,  g_V);

    const int nx2 = MROWS * 512;   // input pairs
    const int nw2 = HIDc * 512;    // weight pairs
    dim3 gp(HIDc / 128, MROWS / 64);             // (8, 128)

    // Q projection
    presplit_kernel<<<(nx2 + 255) / 256, 256>>>(query, xh, xl, nx2);
    presplit_kernel<<<(nw2 + 255) / 256, 256>>>(w_q, wh, wl, nw2);
    proj_kernel<<<gp, 128>>>(xh, xl, wh, wl, b_q, nullptr, Qh, Ql, 1);
    // K projection
    presplit_kernel<<<(nx2 + 255) / 256, 256>>>(key_in, xh, xl, nx2);
    presplit_kernel<<<(nw2 + 255) / 256, 256>>>(w_k, wh, wl, nw2);
    proj_kernel<<<gp, 128>>>(xh, xl, wh, wl, b_k, nullptr, Kh, Kl, 1);
    // V projection (float output)
    presplit_kernel<<<(nx2 + 255) / 256, 256>>>(value, xh, xl, nx2);
    presplit_kernel<<<(nw2 + 255) / 256, 256>>>(w_v, wh, wl, nw2);
    proj_kernel<<<gp, 128>>>(xh, xl, wh, wl, b_v, V, nullptr, nullptr, 0);

    dim3 gs(BHc, Sc / 128, Sc / 64);             // (64, 16, 32)
    scores_kernel<<<gs, 128>>>(mask, attn);

    reduce_ml_kernel<<<(BHc * Sc) / 256, 256>>>();

    dim3 gv(BHc, Sc / 128);                      // (64, 16)
    pv_kernel<<<gv, 256>>>(attn, V, ctx);
}

// round 8
// speedup vs baseline: 1.9429x; 1.1206x over previous
#include <cuda_runtime.h>
#include <cuda_bf16.h>
#include <math.h>

#define Bc   4
#define Sc   2048
#define HIDc 1024
#define Hc   16
#define Dc   64
#define MROWS (Bc*Sc)        // 8192
#define BHc  (Bc*Hc)         // 64
#define LOG2E 1.4426950408889634f

// ---------------------------------------------------------------------------
// Scratch (allocation-free __device__ globals)
// ---------------------------------------------------------------------------
__device__ unsigned g_xh[(size_t)MROWS * 512];       // input  split hi (pairs)
__device__ unsigned g_xl[(size_t)MROWS * 512];       // input  split lo
__device__ unsigned g_wh[(size_t)HIDc * 512];        // weight split hi
__device__ unsigned g_wl[(size_t)HIDc * 512];        // weight split lo
__device__ unsigned g_Qh[(size_t)BHc * Sc * 32];     // Q packed bf16 hi pairs
__device__ unsigned g_Ql[(size_t)BHc * Sc * 32];
__device__ unsigned g_Kh[(size_t)BHc * Sc * 32];
__device__ unsigned g_Kl[(size_t)BHc * Sc * 32];
__device__ float    g_V [(size_t)BHc * Sc * Dc];
__device__ float    g_pm[(size_t)BHc * Sc * 32];     // partial max per 64-col block
__device__ float    g_pl[(size_t)BHc * Sc * 32];     // partial sumexp
__device__ float    g_M [(size_t)BHc * Sc];
__device__ float    g_Li[(size_t)BHc * Sc];

// ---------------------------------------------------------------------------
// helpers
// ---------------------------------------------------------------------------
__device__ __forceinline__ unsigned f2tf32(float x) {
    unsigned r;
    asm("cvt.rna.tf32.f32 %0, %1;" : "=r"(r) : "f"(x));
    return r;
}
__device__ __forceinline__ void mma_tf32(float c[4], const unsigned a[4], const unsigned b[2]) {
    asm("mma.sync.aligned.m16n8k8.row.col.f32.tf32.tf32.f32 "
        "{%0,%1,%2,%3},{%4,%5,%6,%7},{%8,%9},{%0,%1,%2,%3};"
        : "+f"(c[0]), "+f"(c[1]), "+f"(c[2]), "+f"(c[3])
        : "r"(a[0]), "r"(a[1]), "r"(a[2]), "r"(a[3]), "r"(b[0]), "r"(b[1]));
}
__device__ __forceinline__ void mma_bf16(float c[4], const unsigned a[4], const unsigned b[2]) {
    asm("mma.sync.aligned.m16n8k16.row.col.f32.bf16.bf16.f32 "
        "{%0,%1,%2,%3},{%4,%5,%6,%7},{%8,%9},{%0,%1,%2,%3};"
        : "+f"(c[0]), "+f"(c[1]), "+f"(c[2]), "+f"(c[3])
        : "r"(a[0]), "r"(a[1]), "r"(a[2]), "r"(a[3]), "r"(b[0]), "r"(b[1]));
}
__device__ __forceinline__ void split_pack_bf16(float x, float y, unsigned& h, unsigned& l) {
    __nv_bfloat16 hx = __float2bfloat16(x);
    __nv_bfloat16 hy = __float2bfloat16(y);
    __nv_bfloat162 hp; hp.x = hx; hp.y = hy;
    h = *reinterpret_cast<unsigned*>(&hp);
    __nv_bfloat162 lp = __floats2bfloat162_rn(x - __bfloat162float(hx),
                                              y - __bfloat162float(hy));
    l = *reinterpret_cast<unsigned*>(&lp);
}
__device__ __forceinline__ unsigned smem_u32(const void* p) {
    return (unsigned)__cvta_generic_to_shared(p);
}
__device__ __forceinline__ void cpa16(unsigned s, const void* g) {
    asm volatile("cp.async.ca.shared.global [%0],[%1],16;" :: "r"(s), "l"(g));
}
#define CP_COMMIT() asm volatile("cp.async.commit_group;" ::: "memory")
#define CP_WAIT1()  asm volatile("cp.async.wait_group 1;" ::: "memory")

// ---------------------------------------------------------------------------
// Pre-split: float array -> packed bf16 hi/lo pair arrays
// ---------------------------------------------------------------------------
__global__ __launch_bounds__(256) void presplit_kernel(
    const float* __restrict__ src, unsigned* __restrict__ hi,
    unsigned* __restrict__ lo, int n2)
{
    const int i = blockIdx.x * 256 + threadIdx.x;
    if (i < n2) {
        float2 v = ((const float2*)src)[i];
        unsigned h, l;
        split_pack_bf16(v.x, v.y, h, l);
        hi[i] = h; lo[i] = l;
    }
}

// ---------------------------------------------------------------------------
// Projection: C = X*W^T + bias via bf16x3 mma, cp.async double-buffered.
// CTA 64x128, 4 warps (2m x 2n). BK = 8 pairs (16 floats) per stage.
// SMEM row-major [row][pair], stride 12 (conflict-free: g*12+t4 distinct).
// ---------------------------------------------------------------------------
__global__ __launch_bounds__(128) void proj_kernel(
    const unsigned* __restrict__ Xh, const unsigned* __restrict__ Xl,
    const unsigned* __restrict__ Wh, const unsigned* __restrict__ Wl,
    const float* __restrict__ bias,
    float* __restrict__ outf, unsigned* __restrict__ outh,
    unsigned* __restrict__ outl, int mode)
{
    __shared__ unsigned Ah[2][64][12], Al[2][64][12];
    __shared__ unsigned Bh[2][128][12], Bl[2][128][12];

    const int tid  = threadIdx.x;
    const int lane = tid & 31;
    const int warp = tid >> 5;
    const int g    = lane >> 2;
    const int t4   = lane & 3;
    const int wm   = (warp >> 1) * 32;
    const int wn   = (warp & 1) * 64;
    const int m0   = blockIdx.y * 64;
    const int n0   = blockIdx.x * 128;

    const int arow = tid >> 1;            // 0..63
    const int ach  = (tid & 1) * 4;       // chunk 0/4

    float acc[2][8][4] = {};

    // prologue: stage 0
    {
        const size_t ga = (size_t)(m0 + arow) * 512 + ach;
        cpa16(smem_u32(&Ah[0][arow][ach]), &Xh[ga]);
        cpa16(smem_u32(&Al[0][arow][ach]), &Xl[ga]);
        #pragma unroll
        for (int it = 0; it < 2; it++) {
            const int idx = tid + it * 128;
            const int row = idx >> 1, ch = (idx & 1) * 4;
            const size_t gb = (size_t)(n0 + row) * 512 + ch;
            cpa16(smem_u32(&Bh[0][row][ch]), &Wh[gb]);
            cpa16(smem_u32(&Bl[0][row][ch]), &Wl[gb]);
        }
        CP_COMMIT();
    }

    for (int it0 = 0; it0 < 64; it0++) {
        if (it0 + 1 < 64) {
            const int s = (it0 + 1) & 1;
            const int k0p = (it0 + 1) * 8;
            const size_t ga = (size_t)(m0 + arow) * 512 + k0p + ach;
            cpa16(smem_u32(&Ah[s][arow][ach]), &Xh[ga]);
            cpa16(smem_u32(&Al[s][arow][ach]), &Xl[ga]);
            #pragma unroll
            for (int it = 0; it < 2; it++) {
                const int idx = tid + it * 128;
                const int row = idx >> 1, ch = (idx & 1) * 4;
                const size_t gb = (size_t)(n0 + row) * 512 + k0p + ch;
                cpa16(smem_u32(&Bh[s][row][ch]), &Wh[gb]);
                cpa16(smem_u32(&Bl[s][row][ch]), &Wl[gb]);
            }
        }
        CP_COMMIT();
        CP_WAIT1();
        __syncthreads();

        const int b = it0 & 1;
        unsigned ah[2][4], al_[2][4];
        #pragma unroll
        for (int i = 0; i < 2; i++) {
            const int r = wm + i * 16 + g;
            ah[i][0]  = Ah[b][r][t4];     ah[i][1]  = Ah[b][r + 8][t4];
            ah[i][2]  = Ah[b][r][t4 + 4]; ah[i][3]  = Ah[b][r + 8][t4 + 4];
            al_[i][0] = Al[b][r][t4];     al_[i][1] = Al[b][r + 8][t4];
            al_[i][2] = Al[b][r][t4 + 4]; al_[i][3] = Al[b][r + 8][t4 + 4];
        }
        #pragma unroll
        for (int j = 0; j < 8; j++) {
            const int c = wn + j * 8 + g;
            unsigned bh_[2] = {Bh[b][c][t4], Bh[b][c][t4 + 4]};
            unsigned bl_[2] = {Bl[b][c][t4], Bl[b][c][t4 + 4]};
            #pragma unroll
            for (int i = 0; i < 2; i++) {
                mma_bf16(acc[i][j], al_[i], bh_);
                mma_bf16(acc[i][j], ah[i], bl_);
                mma_bf16(acc[i][j], ah[i], bh_);
            }
        }
        __syncthreads();
    }

    #pragma unroll
    for (int i = 0; i < 2; i++) {
        #pragma unroll
        for (int j = 0; j < 8; j++) {
            const int ng = n0 + wn + j * 8 + t4 * 2;
            const int h = ng >> 6;
            const int d = ng & 63;
            const float bv0 = bias[ng];
            const float bv1 = bias[ng + 1];
            const int m1 = m0 + wm + i * 16 + g;
            const int m2 = m1 + 8;
            float v0 = acc[i][j][0] + bv0, v1 = acc[i][j][1] + bv1;
            float v2 = acc[i][j][2] + bv0, v3 = acc[i][j][3] + bv1;
            if (mode) {
                const int d2 = d >> 1;
                unsigned hh, ll;
                {
                    const int b_ = m1 >> 11, s = m1 & 2047;
                    const size_t o = ((size_t)(b_ * 16 + h) * 2048 + s) * 32 + d2;
                    split_pack_bf16(v0, v1, hh, ll);
                    outh[o] = hh; outl[o] = ll;
                }
                {
                    const int b_ = m2 >> 11, s = m2 & 2047;
                    const size_t o = ((size_t)(b_ * 16 + h) * 2048 + s) * 32 + d2;
                    split_pack_bf16(v2, v3, hh, ll);
                    outh[o] = hh; outl[o] = ll;
                }
            } else {
                {
                    const int b_ = m1 >> 11, s = m1 & 2047;
                    *(float2*)&outf[(((size_t)b_ * 16 + h) * 2048 + s) * 64 + d] =
                        make_float2(v0, v1);
                }
                {
                    const int b_ = m2 >> 11, s = m2 & 2047;
                    *(float2*)&outf[(((size_t)b_ * 16 + h) * 2048 + s) * 64 + d] =
                        make_float2(v2, v3);
                }
            }
        }
    }
}

// ---------------------------------------------------------------------------
// Scores: s = scale*Q.K^T via bf16x3, cp.async double-buffered (4 k-stages),
// mask fill, store raw s, emit per-row per-64-col (max, sumexp) partials.
// CTA 64x128, 4 warps (2m x 2n). Grid: (bh, ntile128=16, mtile64=32).
// ---------------------------------------------------------------------------
__global__ __launch_bounds__(128) void scores_kernel(
    const int* __restrict__ mask, float* __restrict__ attn)
{
    const int bh = blockIdx.x;
    const int n0 = blockIdx.y * 128;
    const int m0 = blockIdx.z * 64;
    const unsigned* Qh_g = g_Qh + (size_t)bh * Sc * 32;
    const unsigned* Ql_g = g_Ql + (size_t)bh * Sc * 32;
    const unsigned* Kh_g = g_Kh + (size_t)bh * Sc * 32;
    const unsigned* Kl_g = g_Kl + (size_t)bh * Sc * 32;
    float* Ph = attn + (size_t)bh * Sc * Sc;

    __shared__ unsigned Ah[2][64][12], Al[2][64][12];
    __shared__ unsigned Bh[2][128][12], Bl[2][128][12];

    const int tid  = threadIdx.x;
    const int lane = tid & 31;
    const int warp = tid >> 5;
    const int g    = lane >> 2;
    const int t4   = lane & 3;
    const int wm   = (warp >> 1) * 32;
    const int wn   = (warp & 1) * 64;

    const int arow = tid >> 1;
    const int ach  = (tid & 1) * 4;

    float acc[2][8][4] = {};

    {
        const size_t ga = (size_t)(m0 + arow) * 32 + ach;
        cpa16(smem_u32(&Ah[0][arow][ach]), &Qh_g[ga]);
        cpa16(smem_u32(&Al[0][arow][ach]), &Ql_g[ga]);
        #pragma unroll
        for (int it = 0; it < 2; it++) {
            const int idx = tid + it * 128;
            const int row = idx >> 1, ch = (idx & 1) * 4;
            const size_t gb = (size_t)(n0 + row) * 32 + ch;
            cpa16(smem_u32(&Bh[0][row][ch]), &Kh_g[gb]);
            cpa16(smem_u32(&Bl[0][row][ch]), &Kl_g[gb]);
        }
        CP_COMMIT();
    }

    #pragma unroll
    for (int it0 = 0; it0 < 4; it0++) {
        if (it0 + 1 < 4) {
            const int s = (it0 + 1) & 1;
            const int k0p = (it0 + 1) * 8;
            const size_t ga = (size_t)(m0 + arow) * 32 + k0p + ach;
            cpa16(smem_u32(&Ah[s][arow][ach]), &Qh_g[ga]);
            cpa16(smem_u32(&Al[s][arow][ach]), &Ql_g[ga]);
            #pragma unroll
            for (int it = 0; it < 2; it++) {
                const int idx = tid + it * 128;
                const int row = idx >> 1, ch = (idx & 1) * 4;
                const size_t gb = (size_t)(n0 + row) * 32 + k0p + ch;
                cpa16(smem_u32(&Bh[s][row][ch]), &Kh_g[gb]);
                cpa16(smem_u32(&Bl[s][row][ch]), &Kl_g[gb]);
            }
        }
        CP_COMMIT();
        CP_WAIT1();
        __syncthreads();

        const int b = it0 & 1;
        unsigned ah[2][4], al_[2][4];
        #pragma unroll
        for (int i = 0; i < 2; i++) {
            const int r = wm + i * 16 + g;
            ah[i][0]  = Ah[b][r][t4];     ah[i][1]  = Ah[b][r + 8][t4];
            ah[i][2]  = Ah[b][r][t4 + 4]; ah[i][3]  = Ah[b][r + 8][t4 + 4];
            al_[i][0] = Al[b][r][t4];     al_[i][1] = Al[b][r + 8][t4];
            al_[i][2] = Al[b][r][t4 + 4]; al_[i][3] = Al[b][r + 8][t4 + 4];
        }
        #pragma unroll
        for (int j = 0; j < 8; j++) {
            const int c = wn + j * 8 + g;
            unsigned bh_[2] = {Bh[b][c][t4], Bh[b][c][t4 + 4]};
            unsigned bl_[2] = {Bl[b][c][t4], Bl[b][c][t4 + 4]};
            #pragma unroll
            for (int i = 0; i < 2; i++) {
                mma_bf16(acc[i][j], al_[i], bh_);
                mma_bf16(acc[i][j], ah[i], bl_);
                mma_bf16(acc[i][j], ah[i], bh_);
            }
        }
        __syncthreads();
    }

    // epilogue: scale + mask + store raw s; per-row (max,sumexp) over 64 cols
    const int b_ = bh >> 4;
    const int* mb = mask + (size_t)b_ * Sc * Sc;
    const float scale = 0.125f;
    const int nt = blockIdx.y * 2 + (wn >> 6);

    #pragma unroll
    for (int i = 0; i < 2; i++) {
        const int r0 = m0 + wm + i * 16 + g;
        const int r1 = r0 + 8;
        float mx0 = -3.4e38f, mx1 = -3.4e38f;
        #pragma unroll
        for (int j = 0; j < 8; j++) {
            const int col = n0 + wn + j * 8 + t4 * 2;
            const int2 mm0 = *(const int2*)&mb[(size_t)r0 * Sc + col];
            const int2 mm1 = *(const int2*)&mb[(size_t)r1 * Sc + col];
            acc[i][j][0] = mm0.x ? acc[i][j][0] * scale : -1e9f;
            acc[i][j][1] = mm0.y ? acc[i][j][1] * scale : -1e9f;
            acc[i][j][2] = mm1.x ? acc[i][j][2] * scale : -1e9f;
            acc[i][j][3] = mm1.y ? acc[i][j][3] * scale : -1e9f;
            *(float2*)&Ph[(size_t)r0 * Sc + col] = make_float2(acc[i][j][0], acc[i][j][1]);
            *(float2*)&Ph[(size_t)r1 * Sc + col] = make_float2(acc[i][j][2], acc[i][j][3]);
            mx0 = fmaxf(mx0, fmaxf(acc[i][j][0], acc[i][j][1]));
            mx1 = fmaxf(mx1, fmaxf(acc[i][j][2], acc[i][j][3]));
        }
        mx0 = fmaxf(mx0, __shfl_xor_sync(0xFFFFFFFFu, mx0, 1));
        mx0 = fmaxf(mx0, __shfl_xor_sync(0xFFFFFFFFu, mx0, 2));
        mx1 = fmaxf(mx1, __shfl_xor_sync(0xFFFFFFFFu, mx1, 1));
        mx1 = fmaxf(mx1, __shfl_xor_sync(0xFFFFFFFFu, mx1, 2));

        float s0 = 0.0f, s1 = 0.0f;
        #pragma unroll
        for (int j = 0; j < 8; j++) {
            s0 += exp2f((acc[i][j][0] - mx0) * LOG2E) + exp2f((acc[i][j][1] - mx0) * LOG2E);
            s1 += exp2f((acc[i][j][2] - mx1) * LOG2E) + exp2f((acc[i][j][3] - mx1) * LOG2E);
        }
        s0 += __shfl_xor_sync(0xFFFFFFFFu, s0, 1);
        s0 += __shfl_xor_sync(0xFFFFFFFFu, s0, 2);
        s1 += __shfl_xor_sync(0xFFFFFFFFu, s1, 1);
        s1 += __shfl_xor_sync(0xFFFFFFFFu, s1, 2);

        if (t4 == 0) {
            g_pm[((size_t)bh * Sc + r0) * 32 + nt] = mx0;
            g_pl[((size_t)bh * Sc + r0) * 32 + nt] = s0;
            g_pm[((size_t)bh * Sc + r1) * 32 + nt] = mx1;
            g_pl[((size_t)bh * Sc + r1) * 32 + nt] = s1;
        }
    }
}

// ---------------------------------------------------------------------------
// Combine 32 (m,l) partials per row -> final m, 1/l
// ---------------------------------------------------------------------------
__global__ __launch_bounds__(256) void reduce_ml_kernel()
{
    const size_t r = (size_t)blockIdx.x * 256 + threadIdx.x;
    float m = -3.4e38f;
    float pm[32];
    #pragma unroll
    for (int t = 0; t < 32; t++) {
        pm[t] = g_pm[r * 32 + t];
        m = fmaxf(m, pm[t]);
    }
    float l = 0.0f;
    #pragma unroll
    for (int t = 0; t < 32; t++)
        l += g_pl[r * 32 + t] * exp2f((pm[t] - m) * LOG2E);
    g_M[r]  = m;
    g_Li[r] = 1.0f / l;
}

// ---------------------------------------------------------------------------
// PV: p = exp(s-m)*invl (attn in place), ctx = p @ V. Single tf32 mma.
// Software-pipelined: next tile's GMEM loads staged in registers during mma.
// CTA 128 rows x 64 cols, 8 warps each 16 rows.
// ---------------------------------------------------------------------------
__global__ __launch_bounds__(256) void pv_kernel(
    float* __restrict__ attn, const float* __restrict__ V,
    float* __restrict__ ctx)
{
    const int bh = blockIdx.x;
    const int m0 = blockIdx.y * 128;
    float* Ph = attn + (size_t)bh * Sc * Sc;
    const float* Vh = V + (size_t)bh * Sc * Dc;

    __shared__ unsigned Ps[32][136];
    __shared__ unsigned Vs[32][72];
    __shared__ float smx[128], sli[128];

    const int tid  = threadIdx.x;
    const int lane = tid & 31;
    const int warp = tid >> 5;
    const int g    = lane >> 2;
    const int t4   = lane & 3;
    const int mw   = warp * 16;

    if (tid < 128) {
        const size_t r = (size_t)bh * Sc + m0 + tid;
        smx[tid] = g_M[r];
        sli[tid] = g_Li[r];
    }
    __syncthreads();

    float acc[8][4] = {};
    float4 sreg[4];
    float4 vreg[2];

    // prologue loads for k0 = 0
    #pragma unroll
    for (int it = 0; it < 4; it++) {
        const int idx = tid + it * 256;
        const int row = idx >> 3;
        const int c4  = (idx & 7) * 4;
        sreg[it] = *(const float4*)&Ph[(size_t)(m0 + row) * Sc + c4];
    }
    #pragma unroll
    for (int it = 0; it < 2; it++) {
        const int idx = tid + it * 256;
        const int vr  = idx >> 4;
        const int vc  = (idx & 15) * 4;
        vreg[it] = *(const float4*)&Vh[(size_t)vr * 64 + vc];
    }

    for (int k0 = 0; k0 < 2048; k0 += 32) {
        // transform staged regs -> smem (+ write normalized attn back)
        #pragma unroll
        for (int it = 0; it < 4; it++) {
            const int idx = tid + it * 256;
            const int row = idx >> 3;
            const int c4  = (idx & 7) * 4;
            const float mr = smx[row];
            const float il = sli[row];
            float4 s = sreg[it];
            float4 p;
            p.x = exp2f((s.x - mr) * LOG2E) * il;
            p.y = exp2f((s.y - mr) * LOG2E) * il;
            p.z = exp2f((s.z - mr) * LOG2E) * il;
            p.w = exp2f((s.w - mr) * LOG2E) * il;
            *(float4*)&Ph[(size_t)(m0 + row) * Sc + k0 + c4] = p;
            Ps[c4 + 0][row] = f2tf32(p.x);
            Ps[c4 + 1][row] = f2tf32(p.y);
            Ps[c4 + 2][row] = f2tf32(p.z);
            Ps[c4 + 3][row] = f2tf32(p.w);
        }
        #pragma unroll
        for (int it = 0; it < 2; it++) {
            const int idx = tid + it * 256;
            const int vr  = idx >> 4;
            const int vc  = (idx & 15) * 4;
            float4 v = vreg[it];
            Vs[vr][vc + 0] = f2tf32(v.x);
            Vs[vr][vc + 1] = f2tf32(v.y);
            Vs[vr][vc + 2] = f2tf32(v.z);
            Vs[vr][vc + 3] = f2tf32(v.w);
        }
        __syncthreads();

        // prefetch next tile into registers (overlaps with mma below)
        if (k0 + 32 < 2048) {
            #pragma unroll
            for (int it = 0; it < 4; it++) {
                const int idx = tid + it * 256;
                const int row = idx >> 3;
                const int c4  = (idx & 7) * 4;
                sreg[it] = *(const float4*)&Ph[(size_t)(m0 + row) * Sc + k0 + 32 + c4];
            }
            #pragma unroll
            for (int it = 0; it < 2; it++) {
                const int idx = tid + it * 256;
                const int vr  = idx >> 4;
                const int vc  = (idx & 15) * 4;
                vreg[it] = *(const float4*)&Vh[(size_t)(k0 + 32 + vr) * 64 + vc];
            }
        }

        #pragma unroll
        for (int ks = 0; ks < 4; ks++) {
            const int kb = ks * 8;
            unsigned a[4];
            const int r = mw + g;
            a[0] = Ps[kb + t4    ][r];
            a[1] = Ps[kb + t4    ][r + 8];
            a[2] = Ps[kb + t4 + 4][r];
            a[3] = Ps[kb + t4 + 4][r + 8];
            #pragma unroll
            for (int j = 0; j < 8; j++) {
                unsigned b[2];
                b[0] = Vs[kb + t4    ][j * 8 + g];
                b[1] = Vs[kb + t4 + 4][j * 8 + g];
                mma_tf32(acc[j], a, b);
            }
        }
        __syncthreads();
    }

    const int b_ = bh >> 4;
    const int h  = bh & 15;
    const int r0 = m0 + mw + g;
    const int r1 = r0 + 8;
    #pragma unroll
    for (int j = 0; j < 8; j++) {
        const int d = j * 8 + t4 * 2;
        *(float2*)&ctx[((size_t)b_ * 2048 + r0) * 1024 + h * 64 + d] =
            make_float2(acc[j][0], acc[j][1]);
        *(float2*)&ctx[((size_t)b_ * 2048 + r1) * 1024 + h * 64 + d] =
            make_float2(acc[j][2], acc[j][3]);
    }
}

// ---------------------------------------------------------------------------
extern "C" void kernel_launch(void* const* d_in, const int* in_sizes, int n_in,
                              void* d_out, int out_size)
{
    (void)in_sizes; (void)n_in; (void)out_size;

    const float* query  = (const float*)d_in[0];
    const float* key_in = (const float*)d_in[1];
    const float* value  = (const float*)d_in[2];
    const int*   mask   = (const int*)  d_in[3];
    const float* w_q    = (const float*)d_in[4];
    const float* b_q    = (const float*)d_in[5];
    const float* w_k    = (const float*)d_in[6];
    const float* b_k    = (const float*)d_in[7];
    const float* w_v    = (const float*)d_in[8];
    const float* b_v    = (const float*)d_in[9];

    float* ctx  = (float*)d_out;
    float* attn = (float*)d_out + (size_t)Bc * Sc * HIDc;

    unsigned *xh, *xl, *wh, *wl, *Qh, *Ql, *Kh, *Kl;
    float *V;
    cudaGetSymbolAddress((void**)&xh, g_xh);
    cudaGetSymbolAddress((void**)&xl, g_xl);
    cudaGetSymbolAddress((void**)&wh, g_wh);
    cudaGetSymbolAddress((void**)&wl, g_wl);
    cudaGetSymbolAddress((void**)&Qh, g_Qh);
    cudaGetSymbolAddress((void**)&Ql, g_Ql);
    cudaGetSymbolAddress((void**)&Kh, g_Kh);
    cudaGetSymbolAddress((void**)&Kl, g_Kl);
    cudaGetSymbolAddress((void**)&V,  g_V);

    const int nx2 = MROWS * 512;
    const int nw2 = HIDc * 512;
    dim3 gp(HIDc / 128, MROWS / 64);             // (8, 128)

    presplit_kernel<<<(nx2 + 255) / 256, 256>>>(query, xh, xl, nx2);
    presplit_kernel<<<(nw2 + 255) / 256, 256>>>(w_q, wh, wl, nw2);
    proj_kernel<<<gp, 128>>>(xh, xl, wh, wl, b_q, nullptr, Qh, Ql, 1);

    presplit_kernel<<<(nx2 + 255) / 256, 256>>>(key_in, xh, xl, nx2);
    presplit_kernel<<<(nw2 + 255) / 256, 256>>>(w_k, wh, wl, nw2);
    proj_kernel<<<gp, 128>>>(xh, xl, wh, wl, b_k, nullptr, Kh, Kl, 1);

    presplit_kernel<<<(nx2 + 255) / 256, 256>>>(value, xh, xl, nx2);
    presplit_kernel<<<(nw2 + 255) / 256, 256>>>(w_v, wh, wl, nw2);
    proj_kernel<<<gp, 128>>>(xh, xl, wh, wl, b_v, V, nullptr, nullptr, 0);

    dim3 gs(BHc, Sc / 128, Sc / 64);             // (64, 16, 32)
    scores_kernel<<<gs, 128>>>(mask, attn);

    reduce_ml_kernel<<<(BHc * Sc) / 256, 256>>>();

    dim3 gv(BHc, Sc / 128);                      // (64, 16)
    pv_kernel<<<gv, 256>>>(attn, V, ctx);
}